// round 2
// baseline (speedup 1.0000x reference)
#include <cuda_runtime.h>

// GeneralizedCrossEntropy — only spatial columns 0..20 of each batch are used
// (targets values are class indices < C=21, used as column indices into the
// [C, H*W] flattened probability map).
//
// loss[k] = (1/B) * sum_b (1 - softmax_c(logits[b, :, pos])[k] ^ 0.8) / 0.8
//           with pos = targets[b*H*W + k]
//
// NOTE: JAX without x64 downcasts randint(int64) to int32 — targets are int32.

#define GCE_B 16
#define GCE_C 21
#define GCE_HW (512 * 512)
#define GCE_Q 0.8f

__global__ void gce_kernel(const float* __restrict__ logits,
                           const int* __restrict__ targets,
                           float* __restrict__ out) {
    __shared__ float acc[GCE_C];
    const int tid = threadIdx.x;

    if (tid < GCE_C) acc[tid] = 0.0f;
    __syncthreads();

    if (tid < GCE_B * GCE_C) {
        const int b = tid / GCE_C;
        const int k = tid % GCE_C;

        // column index into the flattened [C, H*W] map; value in [0, C)
        int pos = targets[b * GCE_HW + k];
        // defensive clamp: a wrong value gives a wrong (checked) answer,
        // never an illegal access
        pos = min(max(pos, 0), GCE_HW - 1);

        const float* base = logits + (long long)b * GCE_C * GCE_HW + pos;

        float x[GCE_C];
        float m = -1e30f;
#pragma unroll
        for (int c = 0; c < GCE_C; c++) {
            x[c] = base[(long long)c * GCE_HW];
            m = fmaxf(m, x[c]);
        }
        float s = 0.0f;
#pragma unroll
        for (int c = 0; c < GCE_C; c++) {
            s += expf(x[c] - m);
        }
        const float d = expf(x[k] - m) / s;
        const float term = (1.0f - powf(d, GCE_Q)) / GCE_Q;

        atomicAdd(&acc[k], term);
    }
    __syncthreads();

    if (tid < GCE_C) {
        out[tid] = acc[tid] * (1.0f / (float)GCE_B);
    }
}

extern "C" void kernel_launch(void* const* d_in, const int* in_sizes, int n_in,
                              void* d_out, int out_size) {
    const float* logits = (const float*)d_in[0];
    const int* targets = (const int*)d_in[1];
    float* out = (float*)d_out;

    gce_kernel<<<1, 352>>>(logits, targets, out);
}

// round 3
// speedup vs baseline: 1.0386x; 1.0386x over previous
#include <cuda_runtime.h>

// GeneralizedCrossEntropy — only spatial columns 0..20 of each batch are used.
// loss[k] = (1/B) * sum_b (1 - softmax_c(logits[b, :, pos])[k] ^ 0.8) / 0.8
//           with pos = targets[b*H*W + k], pos in [0, C)
//
// R3: one warp per (b,k) pair across 336 blocks so the fully-uncoalesced
// 1MB-strided loads spread over ~148 SMs instead of queueing ~7056 L1tex
// wavefronts on one SM. Lane c loads x[c]; warp shuffles do max/sum.

#define GCE_B 16
#define GCE_C 21
#define GCE_HW (512 * 512)
#define GCE_Q 0.8f

__device__ float g_terms[GCE_B * GCE_C];

__global__ void gce_columns(const float* __restrict__ logits,
                            const int* __restrict__ targets) {
    const int pair = blockIdx.x;          // 0..335
    const int b = pair / GCE_C;
    const int k = pair % GCE_C;
    const int lane = threadIdx.x;         // 0..31

    int pos = 0;
    if (lane == 0) {
        pos = targets[b * GCE_HW + k];
        pos = min(max(pos, 0), GCE_HW - 1);
    }
    pos = __shfl_sync(0xFFFFFFFF, pos, 0);

    // lane c (< C) loads logits[b, c, pos]
    float x = -1e30f;
    if (lane < GCE_C) {
        x = logits[(long long)b * GCE_C * GCE_HW + (long long)lane * GCE_HW + pos];
    }

    // warp max
    float m = x;
#pragma unroll
    for (int off = 16; off > 0; off >>= 1)
        m = fmaxf(m, __shfl_xor_sync(0xFFFFFFFF, m, off));

    // exp and warp sum (lanes >= C contribute exp(-1e30 - m) == 0)
    float e = __expf(x - m) * (lane < GCE_C ? 1.0f : 0.0f);
    // use precise expf for accuracy of the selected term; recompute below.
    e = (lane < GCE_C) ? expf(x - m) : 0.0f;
    float s = e;
#pragma unroll
    for (int off = 16; off > 0; off >>= 1)
        s += __shfl_xor_sync(0xFFFFFFFF, s, off);

    // probability of class k for this pair
    float ek = __shfl_sync(0xFFFFFFFF, e, k);

    if (lane == 0) {
        float d = ek / s;
        g_terms[pair] = (1.0f - powf(d, GCE_Q)) / GCE_Q;
    }
}

__global__ void gce_reduce(float* __restrict__ out) {
    const int k = threadIdx.x;            // 0..20
    if (k < GCE_C) {
        float acc = 0.0f;
#pragma unroll
        for (int b = 0; b < GCE_B; b++)
            acc += g_terms[b * GCE_C + k];
        out[k] = acc * (1.0f / (float)GCE_B);
    }
}

extern "C" void kernel_launch(void* const* d_in, const int* in_sizes, int n_in,
                              void* d_out, int out_size) {
    const float* logits = (const float*)d_in[0];
    const int* targets = (const int*)d_in[1];
    float* out = (float*)d_out;

    gce_columns<<<GCE_B * GCE_C, 32>>>(logits, targets);
    gce_reduce<<<1, 32>>>(out);
}